// round 1
// baseline (speedup 1.0000x reference)
#include <cuda_runtime.h>
#include <cstdint>

// Problem constants
#define BB      16
#define NC      1024
#define NF      4096
#define M_FINE  (BB * NF)       // 65536 fine points
#define CIN     256
#define CSKIP   128
#define C0      384             // CIN + CSKIP
#define HID     512

// Scratch (no cudaMalloc allowed -> __device__ globals)
__device__ float g_xi[(size_t)M_FINE * C0];    // concat( knn_interp(x), x_skip )  ~96 MB
__device__ float g_h1[(size_t)M_FINE * HID];   // hidden activation               ~128 MB
__device__ int   g_knn_idx[(size_t)M_FINE * 3];
__device__ float g_knn_w[(size_t)M_FINE * 3];  // normalized weights

// ---------------------------------------------------------------------------
// Kernel 1: brute-force kNN (K=3) per cloud. Coarse positions staged in smem.
// grid = (B, NF/256), block = 256 (one thread per fine point)
// ---------------------------------------------------------------------------
__global__ void knn_kernel(const float* __restrict__ pos,
                           const float* __restrict__ pos_skip) {
    __shared__ float sp[NC * 3];
    const int b = blockIdx.x;
    const float* pbase = pos + (size_t)b * NC * 3;
    for (int i = threadIdx.x; i < NC * 3; i += blockDim.x) sp[i] = pbase[i];
    __syncthreads();

    const int p = b * NF + blockIdx.y * blockDim.x + threadIdx.x;
    const float qx = pos_skip[(size_t)p * 3 + 0];
    const float qy = pos_skip[(size_t)p * 3 + 1];
    const float qz = pos_skip[(size_t)p * 3 + 2];

    float d0 = 1e30f, d1 = 1e30f, d2 = 1e30f;
    int   i0 = 0,     i1 = 0,     i2 = 0;

#pragma unroll 4
    for (int j = 0; j < NC; j++) {
        const float dx = qx - sp[j * 3 + 0];
        const float dy = qy - sp[j * 3 + 1];
        const float dz = qz - sp[j * 3 + 2];
        const float d  = dx * dx + dy * dy + dz * dz;
        if (d < d2) {
            if (d < d1) {
                d2 = d1; i2 = i1;
                if (d < d0) { d1 = d0; i1 = i0; d0 = d; i0 = j; }
                else        { d1 = d;  i1 = j; }
            } else {
                d2 = d; i2 = j;
            }
        }
    }

    const float w0 = 1.0f / fmaxf(d0, 1e-16f);
    const float w1 = 1.0f / fmaxf(d1, 1e-16f);
    const float w2 = 1.0f / fmaxf(d2, 1e-16f);
    const float inv = 1.0f / (w0 + w1 + w2);

    g_knn_idx[(size_t)p * 3 + 0] = b * NC + i0;
    g_knn_idx[(size_t)p * 3 + 1] = b * NC + i1;
    g_knn_idx[(size_t)p * 3 + 2] = b * NC + i2;
    g_knn_w  [(size_t)p * 3 + 0] = w0 * inv;
    g_knn_w  [(size_t)p * 3 + 1] = w1 * inv;
    g_knn_w  [(size_t)p * 3 + 2] = w2 * inv;
}

// ---------------------------------------------------------------------------
// Kernel 2: gather + weighted sum + concat with x_skip -> g_xi [M, 384]
// grid = M_FINE blocks, block = 128 threads (coalesced over channels)
// ---------------------------------------------------------------------------
__global__ void gather_kernel(const float* __restrict__ x,
                              const float* __restrict__ x_skip) {
    const int p = blockIdx.x;
    const int t = threadIdx.x;
    const int   i0 = g_knn_idx[(size_t)p * 3 + 0];
    const int   i1 = g_knn_idx[(size_t)p * 3 + 1];
    const int   i2 = g_knn_idx[(size_t)p * 3 + 2];
    const float w0 = g_knn_w[(size_t)p * 3 + 0];
    const float w1 = g_knn_w[(size_t)p * 3 + 1];
    const float w2 = g_knn_w[(size_t)p * 3 + 2];

    float* out = g_xi + (size_t)p * C0;
    const float* r0 = x + (size_t)i0 * CIN;
    const float* r1 = x + (size_t)i1 * CIN;
    const float* r2 = x + (size_t)i2 * CIN;
#pragma unroll
    for (int c = t; c < CIN; c += 128)
        out[c] = w0 * r0[c] + w1 * r1[c] + w2 * r2[c];
    // skip-channel copy
    out[CIN + t] = x_skip[(size_t)p * CSKIP + t];
}

// ---------------------------------------------------------------------------
// Kernel 3: SGEMM (64x64x16 tiles, 4x4 micro-tiles) fused bias+ReLU+BatchNorm.
// C[M, 512] = BN(ReLU(A[M, KD] @ W[KD, 512] + bias))
// grid = (512/64, M/64), block = 256
// ---------------------------------------------------------------------------
template <int KD>
__global__ void __launch_bounds__(256)
gemm_bn_kernel(const float* __restrict__ A, const float* __restrict__ W,
               const float* __restrict__ bias, const float* __restrict__ gam,
               const float* __restrict__ bet,  const float* __restrict__ mu,
               const float* __restrict__ var,  float* __restrict__ C) {
    __shared__ float As[16][65];   // transposed A tile, padded
    __shared__ float Bs[16][68];   // W tile, padded (68*4 = 272 B, 16B-aligned rows)

    const int tid = threadIdx.x;
    const int tx = tid & 15;       // 0..15 -> N micro-tile
    const int ty = tid >> 4;       // 0..15 -> M micro-tile
    const int bm0 = blockIdx.y * 64;
    const int bn0 = blockIdx.x * 64;

    // load indices
    const int lrow = tid >> 2;            // 0..63   (A tile row)
    const int lkq  = (tid & 3) * 4;       // 0,4,8,12 (A tile k-quad)
    const int bk   = tid >> 4;            // 0..15   (W tile row)
    const int bc   = (tid & 15) * 4;      // 0..60   (W tile col-quad)

    float acc[4][4] = {};

    for (int k0 = 0; k0 < KD; k0 += 16) {
        const float4 av = *(const float4*)(A + (size_t)(bm0 + lrow) * KD + k0 + lkq);
        const float4 bv = *(const float4*)(W + (size_t)(k0 + bk) * HID + bn0 + bc);
        As[lkq + 0][lrow] = av.x;
        As[lkq + 1][lrow] = av.y;
        As[lkq + 2][lrow] = av.z;
        As[lkq + 3][lrow] = av.w;
        *(float4*)&Bs[bk][bc] = bv;
        __syncthreads();

#pragma unroll
        for (int k = 0; k < 16; k++) {
            float a[4], b[4];
#pragma unroll
            for (int i = 0; i < 4; i++) a[i] = As[k][ty * 4 + i];
#pragma unroll
            for (int j = 0; j < 4; j++) b[j] = Bs[k][tx * 4 + j];
#pragma unroll
            for (int i = 0; i < 4; i++)
#pragma unroll
                for (int j = 0; j < 4; j++)
                    acc[i][j] = fmaf(a[i], b[j], acc[i][j]);
        }
        __syncthreads();
    }

    // Fused epilogue: bias -> ReLU -> BN(running stats)
    const int gn = bn0 + tx * 4;
    float s[4], sh[4], bb[4];
#pragma unroll
    for (int j = 0; j < 4; j++) {
        const float sv = gam[gn + j] * rsqrtf(var[gn + j] + 1e-5f);
        s[j]  = sv;
        sh[j] = bet[gn + j] - mu[gn + j] * sv;
        bb[j] = bias[gn + j];
    }
#pragma unroll
    for (int i = 0; i < 4; i++) {
        const size_t row = (size_t)(bm0 + ty * 4 + i);
        float4 o;
        float v4[4];
#pragma unroll
        for (int j = 0; j < 4; j++) {
            const float hv = fmaxf(acc[i][j] + bb[j], 0.0f);
            v4[j] = fmaf(hv, s[j], sh[j]);
        }
        o.x = v4[0]; o.y = v4[1]; o.z = v4[2]; o.w = v4[3];
        *(float4*)(C + row * HID + gn) = o;
    }
}

// ---------------------------------------------------------------------------
// Kernel 4: optional tail (pos_skip / batch_skip passthrough outputs)
// ---------------------------------------------------------------------------
__global__ void tail_kernel(const float* __restrict__ pos_skip, float* __restrict__ out,
                            int has_pos, int has_batch) {
    const int i = blockIdx.x * blockDim.x + threadIdx.x;
    size_t off = (size_t)M_FINE * HID;
    if (has_pos) {
        if (i < M_FINE * 3) out[off + i] = pos_skip[i];
        off += (size_t)M_FINE * 3;
    }
    if (has_batch) {
        if (i < M_FINE) out[off + i] = (float)(i / NF);
    }
}

// ---------------------------------------------------------------------------
extern "C" void kernel_launch(void* const* d_in, const int* in_sizes, int n_in,
                              void* d_out, int out_size) {
    const float* x        = (const float*)d_in[0];
    const float* pos      = (const float*)d_in[1];
    // d_in[2] = batch (int64) unused: clouds are contiguous & equal-sized
    const float* x_skip   = (const float*)d_in[3];
    const float* pos_skip = (const float*)d_in[4];
    // d_in[5] = batch_skip (int64) unused
    const float* w1  = (const float*)d_in[6];
    const float* b1  = (const float*)d_in[7];
    const float* g1  = (const float*)d_in[8];
    const float* be1 = (const float*)d_in[9];
    const float* m1  = (const float*)d_in[10];
    const float* v1  = (const float*)d_in[11];
    const float* w2  = (const float*)d_in[12];
    const float* b2  = (const float*)d_in[13];
    const float* g2  = (const float*)d_in[14];
    const float* be2 = (const float*)d_in[15];
    const float* m2  = (const float*)d_in[16];
    const float* v2  = (const float*)d_in[17];
    float* out = (float*)d_out;

    static float* xi_ptr = nullptr;
    static float* h1_ptr = nullptr;
    if (!xi_ptr) {
        cudaGetSymbolAddress((void**)&xi_ptr, g_xi);
        cudaGetSymbolAddress((void**)&h1_ptr, g_h1);
    }

    // 1) kNN
    knn_kernel<<<dim3(BB, NF / 256), 256>>>(pos, pos_skip);
    // 2) interpolate + concat
    gather_kernel<<<M_FINE, 128>>>(x, x_skip);
    // 3) MLP block 1: [M,384] @ [384,512]
    gemm_bn_kernel<C0><<<dim3(HID / 64, M_FINE / 64), 256>>>(
        xi_ptr, w1, b1, g1, be1, m1, v1, h1_ptr);
    // 4) MLP block 2: [M,512] @ [512,512] -> d_out
    gemm_bn_kernel<HID><<<dim3(HID / 64, M_FINE / 64), 256>>>(
        h1_ptr, w2, b2, g2, be2, m2, v2, out);

    // 5) optional passthrough outputs, depending on how the harness flattened
    //    the (h, pos_skip, batch_skip) tuple.
    const long extra = (long)out_size - (long)M_FINE * HID;
    if (extra > 0) {
        const int has_pos   = (extra >= (long)M_FINE * 3) ? 1 : 0;
        const long rem      = extra - (has_pos ? (long)M_FINE * 3 : 0);
        const int has_batch = (rem >= (long)M_FINE) ? 1 : 0;
        const int nmax = has_pos ? M_FINE * 3 : M_FINE;
        tail_kernel<<<(nmax + 255) / 256, 256>>>(pos_skip, out, has_pos, has_batch);
    }
}

// round 2
// speedup vs baseline: 1.4472x; 1.4472x over previous
#include <cuda_runtime.h>
#include <cstdint>

// Problem constants
#define BB      16
#define NC      1024
#define NF      4096
#define M_FINE  (BB * NF)       // 65536 fine points
#define CIN     256
#define CSKIP   128
#define C0      384             // CIN + CSKIP
#define HID     512

// Scratch (no cudaMalloc allowed -> __device__ globals)
__device__ float g_xi[(size_t)M_FINE * C0];    // concat( knn_interp(x), x_skip )
__device__ float g_h1[(size_t)M_FINE * HID];   // hidden activation
__device__ int   g_knn_idx[(size_t)M_FINE * 3];
__device__ float g_knn_w[(size_t)M_FINE * 3];

// ---------------------------------------------------------------------------
// Kernel 1: brute-force kNN (K=3) per cloud. Coarse positions staged in smem.
// ---------------------------------------------------------------------------
__global__ void knn_kernel(const float* __restrict__ pos,
                           const float* __restrict__ pos_skip) {
    __shared__ float sp[NC * 3];
    const int b = blockIdx.x;
    const float* pbase = pos + (size_t)b * NC * 3;
    for (int i = threadIdx.x; i < NC * 3; i += blockDim.x) sp[i] = pbase[i];
    __syncthreads();

    const int p = b * NF + blockIdx.y * blockDim.x + threadIdx.x;
    const float qx = pos_skip[(size_t)p * 3 + 0];
    const float qy = pos_skip[(size_t)p * 3 + 1];
    const float qz = pos_skip[(size_t)p * 3 + 2];

    float d0 = 1e30f, d1 = 1e30f, d2 = 1e30f;
    int   i0 = 0,     i1 = 0,     i2 = 0;

#pragma unroll 4
    for (int j = 0; j < NC; j++) {
        const float dx = qx - sp[j * 3 + 0];
        const float dy = qy - sp[j * 3 + 1];
        const float dz = qz - sp[j * 3 + 2];
        const float d  = dx * dx + dy * dy + dz * dz;
        if (d < d2) {
            if (d < d1) {
                d2 = d1; i2 = i1;
                if (d < d0) { d1 = d0; i1 = i0; d0 = d; i0 = j; }
                else        { d1 = d;  i1 = j; }
            } else {
                d2 = d; i2 = j;
            }
        }
    }

    const float w0 = 1.0f / fmaxf(d0, 1e-16f);
    const float w1 = 1.0f / fmaxf(d1, 1e-16f);
    const float w2 = 1.0f / fmaxf(d2, 1e-16f);
    const float inv = 1.0f / (w0 + w1 + w2);

    g_knn_idx[(size_t)p * 3 + 0] = b * NC + i0;
    g_knn_idx[(size_t)p * 3 + 1] = b * NC + i1;
    g_knn_idx[(size_t)p * 3 + 2] = b * NC + i2;
    g_knn_w  [(size_t)p * 3 + 0] = w0 * inv;
    g_knn_w  [(size_t)p * 3 + 1] = w1 * inv;
    g_knn_w  [(size_t)p * 3 + 2] = w2 * inv;
}

// ---------------------------------------------------------------------------
// Kernel 2: gather + weighted sum + concat with x_skip -> g_xi [M, 384]
// ---------------------------------------------------------------------------
__global__ void gather_kernel(const float* __restrict__ x,
                              const float* __restrict__ x_skip) {
    const int p = blockIdx.x;
    const int t = threadIdx.x;
    const int   i0 = g_knn_idx[(size_t)p * 3 + 0];
    const int   i1 = g_knn_idx[(size_t)p * 3 + 1];
    const int   i2 = g_knn_idx[(size_t)p * 3 + 2];
    const float w0 = g_knn_w[(size_t)p * 3 + 0];
    const float w1 = g_knn_w[(size_t)p * 3 + 1];
    const float w2 = g_knn_w[(size_t)p * 3 + 2];

    float* out = g_xi + (size_t)p * C0;
    const float* r0 = x + (size_t)i0 * CIN;
    const float* r1 = x + (size_t)i1 * CIN;
    const float* r2 = x + (size_t)i2 * CIN;
#pragma unroll
    for (int c = t; c < CIN; c += 128)
        out[c] = w0 * r0[c] + w1 * r1[c] + w2 * r2[c];
    out[CIN + t] = x_skip[(size_t)p * CSKIP + t];
}

// ---------------------------------------------------------------------------
// Kernel 3: SGEMM 128x128x8 tiles, 8x8 spread micro-tiles, double-buffered
// smem + register-staged prefetch. Fused bias+ReLU+BN epilogue.
// C[M, 512] = BN(ReLU(A[M, KD] @ W[KD, 512] + bias))
// grid = (512/128, M/128), block = 256
// ---------------------------------------------------------------------------
template <int KD>
__global__ void __launch_bounds__(256, 2)
gemm_bn_v2(const float* __restrict__ A, const float* __restrict__ W,
           const float* __restrict__ bias, const float* __restrict__ gam,
           const float* __restrict__ bet,  const float* __restrict__ mu,
           const float* __restrict__ var,  float* __restrict__ C) {
    __shared__ float As[2][8][132];   // [buf][k][row], padded pitch (132*4B, rows 16B-aligned)
    __shared__ float Bs[2][8][128];   // [buf][k][col]

    const int tid = threadIdx.x;
    const int tx = tid & 15;          // 0..15 -> N
    const int ty = tid >> 4;          // 0..15 -> M
    const int bm0 = blockIdx.y * 128;
    const int bn0 = blockIdx.x * 128;

    // global-load mapping
    const int arow = tid >> 1;                // 0..127
    const int akq  = (tid & 1) * 4;           // 0 or 4
    const int brow = tid >> 5;                // 0..7
    const int bcol = (tid & 31) * 4;          // 0..124

    const float* Aptr = A + (size_t)(bm0 + arow) * KD + akq;
    const float* Wptr = W + (size_t)brow * HID + bn0 + bcol;

    float4 ar = *(const float4*)(Aptr);
    float4 br = *(const float4*)(Wptr);

    float acc[2][2][4][4] = {};

    // store tile 0
    As[0][akq + 0][arow] = ar.x;
    As[0][akq + 1][arow] = ar.y;
    As[0][akq + 2][arow] = ar.z;
    As[0][akq + 3][arow] = ar.w;
    *(float4*)&Bs[0][brow][bcol] = br;
    __syncthreads();

    const int NT = KD / 8;
    int buf = 0;
#pragma unroll 1
    for (int t = 0; t < NT; t++) {
        if (t + 1 < NT) {   // prefetch next tile into registers
            ar = *(const float4*)(Aptr + (t + 1) * 8);
            br = *(const float4*)(Wptr + (size_t)(t + 1) * 8 * HID);
        }
#pragma unroll
        for (int k = 0; k < 8; k++) {
            const float4 a0 = *(const float4*)&As[buf][k][ty * 4];
            const float4 a1 = *(const float4*)&As[buf][k][64 + ty * 4];
            const float4 b0 = *(const float4*)&Bs[buf][k][tx * 4];
            const float4 b1 = *(const float4*)&Bs[buf][k][64 + tx * 4];
            const float av[2][4] = {{a0.x, a0.y, a0.z, a0.w}, {a1.x, a1.y, a1.z, a1.w}};
            const float bv[2][4] = {{b0.x, b0.y, b0.z, b0.w}, {b1.x, b1.y, b1.z, b1.w}};
#pragma unroll
            for (int mi = 0; mi < 2; mi++)
#pragma unroll
                for (int ni = 0; ni < 2; ni++)
#pragma unroll
                    for (int i = 0; i < 4; i++)
#pragma unroll
                        for (int j = 0; j < 4; j++)
                            acc[mi][ni][i][j] = fmaf(av[mi][i], bv[ni][j], acc[mi][ni][i][j]);
        }
        if (t + 1 < NT) {
            const int nb = buf ^ 1;
            As[nb][akq + 0][arow] = ar.x;
            As[nb][akq + 1][arow] = ar.y;
            As[nb][akq + 2][arow] = ar.z;
            As[nb][akq + 3][arow] = ar.w;
            *(float4*)&Bs[nb][brow][bcol] = br;
        }
        __syncthreads();
        buf ^= 1;
    }

    // Fused epilogue: bias -> ReLU -> BN(running stats)
#pragma unroll
    for (int ni = 0; ni < 2; ni++) {
        const int gn = bn0 + ni * 64 + tx * 4;
        float s[4], sh[4], bb[4];
#pragma unroll
        for (int j = 0; j < 4; j++) {
            const float sv = gam[gn + j] * rsqrtf(var[gn + j] + 1e-5f);
            s[j]  = sv;
            sh[j] = bet[gn + j] - mu[gn + j] * sv;
            bb[j] = bias[gn + j];
        }
#pragma unroll
        for (int mi = 0; mi < 2; mi++)
#pragma unroll
            for (int i = 0; i < 4; i++) {
                const size_t row = (size_t)(bm0 + mi * 64 + ty * 4 + i);
                float4 o;
                o.x = fmaf(fmaxf(acc[mi][ni][i][0] + bb[0], 0.0f), s[0], sh[0]);
                o.y = fmaf(fmaxf(acc[mi][ni][i][1] + bb[1], 0.0f), s[1], sh[1]);
                o.z = fmaf(fmaxf(acc[mi][ni][i][2] + bb[2], 0.0f), s[2], sh[2]);
                o.w = fmaf(fmaxf(acc[mi][ni][i][3] + bb[3], 0.0f), s[3], sh[3]);
                *(float4*)(C + row * HID + gn) = o;
            }
    }
}

// ---------------------------------------------------------------------------
// Kernel 4: optional tail (pos_skip / batch_skip passthrough outputs)
// ---------------------------------------------------------------------------
__global__ void tail_kernel(const float* __restrict__ pos_skip, float* __restrict__ out,
                            int has_pos, int has_batch) {
    const int i = blockIdx.x * blockDim.x + threadIdx.x;
    size_t off = (size_t)M_FINE * HID;
    if (has_pos) {
        if (i < M_FINE * 3) out[off + i] = pos_skip[i];
        off += (size_t)M_FINE * 3;
    }
    if (has_batch) {
        if (i < M_FINE) out[off + i] = (float)(i / NF);
    }
}

// ---------------------------------------------------------------------------
extern "C" void kernel_launch(void* const* d_in, const int* in_sizes, int n_in,
                              void* d_out, int out_size) {
    const float* x        = (const float*)d_in[0];
    const float* pos      = (const float*)d_in[1];
    const float* x_skip   = (const float*)d_in[3];
    const float* pos_skip = (const float*)d_in[4];
    const float* w1  = (const float*)d_in[6];
    const float* b1  = (const float*)d_in[7];
    const float* g1  = (const float*)d_in[8];
    const float* be1 = (const float*)d_in[9];
    const float* m1  = (const float*)d_in[10];
    const float* v1  = (const float*)d_in[11];
    const float* w2  = (const float*)d_in[12];
    const float* b2  = (const float*)d_in[13];
    const float* g2  = (const float*)d_in[14];
    const float* be2 = (const float*)d_in[15];
    const float* m2  = (const float*)d_in[16];
    const float* v2  = (const float*)d_in[17];
    float* out = (float*)d_out;

    static float* xi_ptr = nullptr;
    static float* h1_ptr = nullptr;
    if (!xi_ptr) {
        cudaGetSymbolAddress((void**)&xi_ptr, g_xi);
        cudaGetSymbolAddress((void**)&h1_ptr, g_h1);
    }

    // 1) kNN
    knn_kernel<<<dim3(BB, NF / 256), 256>>>(pos, pos_skip);
    // 2) interpolate + concat
    gather_kernel<<<M_FINE, 128>>>(x, x_skip);
    // 3) MLP block 1: [M,384] @ [384,512]
    gemm_bn_v2<C0><<<dim3(HID / 128, M_FINE / 128), 256>>>(
        xi_ptr, w1, b1, g1, be1, m1, v1, h1_ptr);
    // 4) MLP block 2: [M,512] @ [512,512] -> d_out
    gemm_bn_v2<HID><<<dim3(HID / 128, M_FINE / 128), 256>>>(
        h1_ptr, w2, b2, g2, be2, m2, v2, out);

    // 5) optional passthrough outputs
    const long extra = (long)out_size - (long)M_FINE * HID;
    if (extra > 0) {
        const int has_pos   = (extra >= (long)M_FINE * 3) ? 1 : 0;
        const long rem      = extra - (has_pos ? (long)M_FINE * 3 : 0);
        const int has_batch = (rem >= (long)M_FINE) ? 1 : 0;
        const int nmax = has_pos ? M_FINE * 3 : M_FINE;
        tail_kernel<<<(nmax + 255) / 256, 256>>>(pos_skip, out, has_pos, has_batch);
    }
}

// round 4
// speedup vs baseline: 2.0347x; 1.4060x over previous
#include <cuda_runtime.h>
#include <cuda_bf16.h>
#include <cstdint>

// Problem constants
#define BB      16
#define NC      1024
#define NF      4096
#define M_FINE  (BB * NF)       // 65536
#define CIN     256
#define CSKIP   128
#define C0      384
#define HID     512

// ---------------------------------------------------------------------------
// Device scratch (no cudaMalloc allowed)
// ---------------------------------------------------------------------------
__device__ __nv_bfloat16 g_xi_hi[(size_t)M_FINE * C0];
__device__ __nv_bfloat16 g_xi_lo[(size_t)M_FINE * C0];
__device__ __nv_bfloat16 g_h1_hi[(size_t)M_FINE * HID];
__device__ __nv_bfloat16 g_h1_lo[(size_t)M_FINE * HID];
__device__ __nv_bfloat16 g_wt1_hi[HID * C0];   // [n][k] = w1[k][n]
__device__ __nv_bfloat16 g_wt1_lo[HID * C0];
__device__ __nv_bfloat16 g_wt2_hi[HID * HID];
__device__ __nv_bfloat16 g_wt2_lo[HID * HID];
__device__ int   g_knn_idx[M_FINE * 3];
__device__ float g_knn_w[M_FINE * 3];

// ---------------------------------------------------------------------------
// Baseline-ISA tensor-core helpers (valid in compute_103 PTX)
// ---------------------------------------------------------------------------
__device__ __forceinline__ uint32_t smem_to_u32(const void* p) {
    uint32_t a;
    asm("{ .reg .u64 t; cvta.to.shared.u64 t, %1; cvt.u32.u64 %0, t; }" : "=r"(a) : "l"(p));
    return a;
}
__device__ __forceinline__ void cp_async16(uint32_t saddr, const void* gaddr) {
    asm volatile("cp.async.cg.shared.global [%0], [%1], 16;" :: "r"(saddr), "l"(gaddr));
}
#define CP_COMMIT() asm volatile("cp.async.commit_group;" ::: "memory")
#define CP_WAIT(N)  asm volatile("cp.async.wait_group %0;" :: "n"(N) : "memory")

__device__ __forceinline__ void ldsm_x4(uint32_t* r, uint32_t addr) {
    asm volatile("ldmatrix.sync.aligned.m8n8.x4.shared.b16 {%0,%1,%2,%3}, [%4];"
                 : "=r"(r[0]), "=r"(r[1]), "=r"(r[2]), "=r"(r[3]) : "r"(addr));
}
__device__ __forceinline__ void ldsm_x2(uint32_t* r, uint32_t addr) {
    asm volatile("ldmatrix.sync.aligned.m8n8.x2.shared.b16 {%0,%1}, [%2];"
                 : "=r"(r[0]), "=r"(r[1]) : "r"(addr));
}
__device__ __forceinline__ void mma_bf16(float* c, const uint32_t* a, const uint32_t* b) {
    asm volatile("mma.sync.aligned.m16n8k16.row.col.f32.bf16.bf16.f32 "
                 "{%0,%1,%2,%3}, {%4,%5,%6,%7}, {%8,%9}, {%0,%1,%2,%3};"
                 : "+f"(c[0]), "+f"(c[1]), "+f"(c[2]), "+f"(c[3])
                 : "r"(a[0]), "r"(a[1]), "r"(a[2]), "r"(a[3]), "r"(b[0]), "r"(b[1]));
}
__device__ __forceinline__ void bf16_split(float v, __nv_bfloat16& h, __nv_bfloat16& l) {
    h = __float2bfloat16(v);
    l = __float2bfloat16(v - __bfloat162float(h));
}

// ---------------------------------------------------------------------------
// Weight transpose + bf16 hi/lo split.  wt[n][k] = w[k][n]
// ---------------------------------------------------------------------------
__global__ void wprep_kernel(const float* __restrict__ w, __nv_bfloat16* __restrict__ hi,
                             __nv_bfloat16* __restrict__ lo, int KD) {
    const int i = blockIdx.x * blockDim.x + threadIdx.x;
    if (i >= KD * HID) return;
    const int n = i / KD, k = i % KD;
    const float v = w[(size_t)k * HID + n];
    __nv_bfloat16 h, l;
    bf16_split(v, h, l);
    hi[i] = h; lo[i] = l;
}

// ---------------------------------------------------------------------------
// Kernel 1: brute-force kNN (K=3)
// ---------------------------------------------------------------------------
__global__ void knn_kernel(const float* __restrict__ pos,
                           const float* __restrict__ pos_skip) {
    __shared__ float sp[NC * 3];
    const int b = blockIdx.x;
    const float* pbase = pos + (size_t)b * NC * 3;
    for (int i = threadIdx.x; i < NC * 3; i += blockDim.x) sp[i] = pbase[i];
    __syncthreads();

    const int p = b * NF + blockIdx.y * blockDim.x + threadIdx.x;
    const float qx = pos_skip[(size_t)p * 3 + 0];
    const float qy = pos_skip[(size_t)p * 3 + 1];
    const float qz = pos_skip[(size_t)p * 3 + 2];

    float d0 = 1e30f, d1 = 1e30f, d2 = 1e30f;
    int   i0 = 0,     i1 = 0,     i2 = 0;
#pragma unroll 4
    for (int j = 0; j < NC; j++) {
        const float dx = qx - sp[j * 3 + 0];
        const float dy = qy - sp[j * 3 + 1];
        const float dz = qz - sp[j * 3 + 2];
        const float d  = dx * dx + dy * dy + dz * dz;
        if (d < d2) {
            if (d < d1) {
                d2 = d1; i2 = i1;
                if (d < d0) { d1 = d0; i1 = i0; d0 = d; i0 = j; }
                else        { d1 = d;  i1 = j; }
            } else { d2 = d; i2 = j; }
        }
    }
    const float w0 = 1.0f / fmaxf(d0, 1e-16f);
    const float w1 = 1.0f / fmaxf(d1, 1e-16f);
    const float w2 = 1.0f / fmaxf(d2, 1e-16f);
    const float inv = 1.0f / (w0 + w1 + w2);
    g_knn_idx[p * 3 + 0] = b * NC + i0;
    g_knn_idx[p * 3 + 1] = b * NC + i1;
    g_knn_idx[p * 3 + 2] = b * NC + i2;
    g_knn_w  [p * 3 + 0] = w0 * inv;
    g_knn_w  [p * 3 + 1] = w1 * inv;
    g_knn_w  [p * 3 + 2] = w2 * inv;
}

// ---------------------------------------------------------------------------
// Kernel 2: gather + interpolate + concat -> bf16 hi/lo [M, 384]
// ---------------------------------------------------------------------------
__global__ void gather_kernel(const float* __restrict__ x,
                              const float* __restrict__ x_skip) {
    const int p = blockIdx.x;
    const int t = threadIdx.x;
    const int   i0 = g_knn_idx[p * 3 + 0];
    const int   i1 = g_knn_idx[p * 3 + 1];
    const int   i2 = g_knn_idx[p * 3 + 2];
    const float w0 = g_knn_w[p * 3 + 0];
    const float w1 = g_knn_w[p * 3 + 1];
    const float w2 = g_knn_w[p * 3 + 2];

    const float* r0 = x + (size_t)i0 * CIN;
    const float* r1 = x + (size_t)i1 * CIN;
    const float* r2 = x + (size_t)i2 * CIN;
    const size_t ob = (size_t)p * C0;
#pragma unroll
    for (int c = t; c < CIN; c += 128) {
        const float v = w0 * r0[c] + w1 * r1[c] + w2 * r2[c];
        __nv_bfloat16 h, l; bf16_split(v, h, l);
        g_xi_hi[ob + c] = h; g_xi_lo[ob + c] = l;
    }
    {
        const float v = x_skip[(size_t)p * CSKIP + t];
        __nv_bfloat16 h, l; bf16_split(v, h, l);
        g_xi_hi[ob + CIN + t] = h; g_xi_lo[ob + CIN + t] = l;
    }
}

// ---------------------------------------------------------------------------
// Kernel 3: bf16 HMMA GEMM (mma.sync m16n8k16), 3-term hi/lo split.
// CTA tile 128x128, 8 warps (2m x 4n), each warp 64x32. K-step 64 halves.
// cp.async double-buffered smem, padded rows (144B) -> conflict-free ldmatrix.
// Fused bias + ReLU + BN epilogue. OUT_BF16: emit hi/lo bf16 for next layer.
// ---------------------------------------------------------------------------
#define RSTRIDE   144                         // bytes per smem row (64 halves + 8 pad)
#define TILE_B    (128 * RSTRIDE)             // 18432 B per tile
#define STAGE_B   (4 * TILE_B)                // AH | AL | BH | BL = 73728 B
#define SMEM_GEMM (2 * STAGE_B)               // 147456 B

template <int KD, int OUT_BF16>
__global__ void __launch_bounds__(256, 1)
gemm_mma(const __nv_bfloat16* __restrict__ Ahi, const __nv_bfloat16* __restrict__ Alo,
         const __nv_bfloat16* __restrict__ Whi, const __nv_bfloat16* __restrict__ Wlo,
         const float* __restrict__ bias, const float* __restrict__ gam,
         const float* __restrict__ bet,  const float* __restrict__ mu,
         const float* __restrict__ var,
         float* __restrict__ Cf, __nv_bfloat16* __restrict__ Chi,
         __nv_bfloat16* __restrict__ Clo) {
    extern __shared__ char smem[];
    const uint32_t sbase = smem_to_u32(smem);
    const int tid  = threadIdx.x;
    const int wid  = tid >> 5, lane = tid & 31;
    const int wm   = wid >> 2;          // 0..1  (64-row slab)
    const int wn   = wid & 3;           // 0..3  (32-col slab)
    const int bm0  = blockIdx.y * 128;
    const int bn0  = blockIdx.x * 128;

    // cp.async mapping: per tile 1024 chunks of 16B; 4 per thread
    const int crow = tid >> 1;                 // 0..127 (two threads per row)
    // each thread covers 4 of the row's 8 chunks
    const int cseg0 = (tid & 1) * 4;           // 0 or 4

    auto load_stage = [&](int kt, int buf) {
        const int k0 = kt * 64;
        const uint32_t stg = sbase + buf * STAGE_B;
        const size_t ga = (size_t)(bm0 + crow) * KD + k0 + cseg0 * 8;
        const size_t gb = (size_t)(bn0 + crow) * KD + k0 + cseg0 * 8;
        const uint32_t so = crow * RSTRIDE + cseg0 * 16;
#pragma unroll
        for (int s = 0; s < 4; s++) {
            cp_async16(stg + 0 * TILE_B + so + s * 16, Ahi + ga + s * 8);
            cp_async16(stg + 1 * TILE_B + so + s * 16, Alo + ga + s * 8);
            cp_async16(stg + 2 * TILE_B + so + s * 16, Whi + gb + s * 8);
            cp_async16(stg + 3 * TILE_B + so + s * 16, Wlo + gb + s * 8);
        }
    };

    float acc[4][4][4] = {};   // [mi][ni][frag]

    // ldmatrix addresses (within current stage)
    const uint32_t a_row = wm * 64 + (lane & 15);          // + mi*16
    const uint32_t a_colb = (lane >> 4) * 16;              // byte offset + kf*32
    const uint32_t b_row = wn * 32 + (lane & 7);           // + ni*8
    const uint32_t b_colb = ((lane >> 3) & 1) * 16;        // byte offset + kf*32

    load_stage(0, 0);
    CP_COMMIT();

    constexpr int NT = KD / 64;
#pragma unroll 1
    for (int t = 0; t < NT; t++) {
        if (t + 1 < NT) { load_stage(t + 1, (t + 1) & 1); CP_COMMIT(); CP_WAIT(1); }
        else            { CP_WAIT(0); }
        __syncthreads();

        const uint32_t stg = sbase + (t & 1) * STAGE_B;
        const uint32_t ah_base = stg + 0 * TILE_B;
        const uint32_t al_base = stg + 1 * TILE_B;
        const uint32_t bh_base = stg + 2 * TILE_B;
        const uint32_t bl_base = stg + 3 * TILE_B;

#pragma unroll
        for (int kf = 0; kf < 4; kf++) {
            uint32_t ah[4][4], al[4][4], bh[4][2], bl[4][2];
#pragma unroll
            for (int mi = 0; mi < 4; mi++) {
                const uint32_t ao = (a_row + mi * 16) * RSTRIDE + kf * 32 + a_colb;
                ldsm_x4(ah[mi], ah_base + ao);
                ldsm_x4(al[mi], al_base + ao);
            }
#pragma unroll
            for (int ni = 0; ni < 4; ni++) {
                const uint32_t bo = (b_row + ni * 8) * RSTRIDE + kf * 32 + b_colb;
                ldsm_x2(bh[ni], bh_base + bo);
                ldsm_x2(bl[ni], bl_base + bo);
            }
#pragma unroll
            for (int mi = 0; mi < 4; mi++)
#pragma unroll
                for (int ni = 0; ni < 4; ni++) {
                    mma_bf16(acc[mi][ni], ah[mi], bh[ni]);
                    mma_bf16(acc[mi][ni], ah[mi], bl[ni]);
                    mma_bf16(acc[mi][ni], al[mi], bh[ni]);
                }
        }
        __syncthreads();
    }

    // ----- fused epilogue: bias -> ReLU -> BN -----
#pragma unroll
    for (int ni = 0; ni < 4; ni++) {
        const int c0 = bn0 + wn * 32 + ni * 8 + (lane & 3) * 2;   // two adjacent cols
        float s0v, s1v, sh0, sh1, bb0, bb1;
        {
            const float sa = gam[c0]     * rsqrtf(var[c0]     + 1e-5f);
            const float sb = gam[c0 + 1] * rsqrtf(var[c0 + 1] + 1e-5f);
            s0v = sa; s1v = sb;
            sh0 = bet[c0]     - mu[c0]     * sa;
            sh1 = bet[c0 + 1] - mu[c0 + 1] * sb;
            bb0 = bias[c0]; bb1 = bias[c0 + 1];
        }
#pragma unroll
        for (int mi = 0; mi < 4; mi++) {
#pragma unroll
            for (int half = 0; half < 2; half++) {
                const int row = bm0 + wm * 64 + mi * 16 + (lane >> 2) + half * 8;
                const float v0 = fmaf(fmaxf(acc[mi][ni][half * 2 + 0] + bb0, 0.0f), s0v, sh0);
                const float v1 = fmaf(fmaxf(acc[mi][ni][half * 2 + 1] + bb1, 0.0f), s1v, sh1);
                if (OUT_BF16) {
                    __nv_bfloat16 h0, l0, h1, l1;
                    bf16_split(v0, h0, l0);
                    bf16_split(v1, h1, l1);
                    const uint32_t ph = ((uint32_t)__bfloat16_as_ushort(h1) << 16) | __bfloat16_as_ushort(h0);
                    const uint32_t pl = ((uint32_t)__bfloat16_as_ushort(l1) << 16) | __bfloat16_as_ushort(l0);
                    *(uint32_t*)(Chi + (size_t)row * HID + c0) = ph;
                    *(uint32_t*)(Clo + (size_t)row * HID + c0) = pl;
                } else {
                    float2 o; o.x = v0; o.y = v1;
                    *(float2*)(Cf + (size_t)row * HID + c0) = o;
                }
            }
        }
    }
}

// ---------------------------------------------------------------------------
// Optional tail (pos_skip / batch_skip passthrough)
// ---------------------------------------------------------------------------
__global__ void tail_kernel(const float* __restrict__ pos_skip, float* __restrict__ out,
                            int has_pos, int has_batch) {
    const int i = blockIdx.x * blockDim.x + threadIdx.x;
    size_t off = (size_t)M_FINE * HID;
    if (has_pos) {
        if (i < M_FINE * 3) out[off + i] = pos_skip[i];
        off += (size_t)M_FINE * 3;
    }
    if (has_batch) {
        if (i < M_FINE) out[off + i] = (float)(i / NF);
    }
}

// ---------------------------------------------------------------------------
extern "C" void kernel_launch(void* const* d_in, const int* in_sizes, int n_in,
                              void* d_out, int out_size) {
    const float* x        = (const float*)d_in[0];
    const float* pos      = (const float*)d_in[1];
    const float* x_skip   = (const float*)d_in[3];
    const float* pos_skip = (const float*)d_in[4];
    const float* w1  = (const float*)d_in[6];
    const float* b1  = (const float*)d_in[7];
    const float* g1  = (const float*)d_in[8];
    const float* be1 = (const float*)d_in[9];
    const float* m1  = (const float*)d_in[10];
    const float* v1  = (const float*)d_in[11];
    const float* w2  = (const float*)d_in[12];
    const float* b2  = (const float*)d_in[13];
    const float* g2  = (const float*)d_in[14];
    const float* be2 = (const float*)d_in[15];
    const float* m2  = (const float*)d_in[16];
    const float* v2  = (const float*)d_in[17];
    float* out = (float*)d_out;

    static __nv_bfloat16 *xi_hi = nullptr, *xi_lo, *h1_hi, *h1_lo,
                         *wt1_hi, *wt1_lo, *wt2_hi, *wt2_lo;
    if (!xi_hi) {
        cudaGetSymbolAddress((void**)&xi_hi, g_xi_hi);
        cudaGetSymbolAddress((void**)&xi_lo, g_xi_lo);
        cudaGetSymbolAddress((void**)&h1_hi, g_h1_hi);
        cudaGetSymbolAddress((void**)&h1_lo, g_h1_lo);
        cudaGetSymbolAddress((void**)&wt1_hi, g_wt1_hi);
        cudaGetSymbolAddress((void**)&wt1_lo, g_wt1_lo);
        cudaGetSymbolAddress((void**)&wt2_hi, g_wt2_hi);
        cudaGetSymbolAddress((void**)&wt2_lo, g_wt2_lo);
        cudaFuncSetAttribute(gemm_mma<C0, 1>,  cudaFuncAttributeMaxDynamicSharedMemorySize, SMEM_GEMM);
        cudaFuncSetAttribute(gemm_mma<HID, 0>, cudaFuncAttributeMaxDynamicSharedMemorySize, SMEM_GEMM);
    }

    // weight prep (transpose + hi/lo split)
    wprep_kernel<<<(C0 * HID + 255) / 256, 256>>>(w1, wt1_hi, wt1_lo, C0);
    wprep_kernel<<<(HID * HID + 255) / 256, 256>>>(w2, wt2_hi, wt2_lo, HID);
    // kNN + interpolate/concat (bf16 hi/lo)
    knn_kernel<<<dim3(BB, NF / 256), 256>>>(pos, pos_skip);
    gather_kernel<<<M_FINE, 128>>>(x, x_skip);
    // MLP block 1: [M,384] @ [384,512] -> h1 (bf16 hi/lo)
    gemm_mma<C0, 1><<<dim3(HID / 128, M_FINE / 128), 256, SMEM_GEMM>>>(
        xi_hi, xi_lo, wt1_hi, wt1_lo, b1, g1, be1, m1, v1,
        nullptr, h1_hi, h1_lo);
    // MLP block 2: [M,512] @ [512,512] -> d_out (fp32)
    gemm_mma<HID, 0><<<dim3(HID / 128, M_FINE / 128), 256, SMEM_GEMM>>>(
        h1_hi, h1_lo, wt2_hi, wt2_lo, b2, g2, be2, m2, v2,
        out, nullptr, nullptr);

    // optional passthrough outputs
    const long extra = (long)out_size - (long)M_FINE * HID;
    if (extra > 0) {
        const int has_pos   = (extra >= (long)M_FINE * 3) ? 1 : 0;
        const long rem      = extra - (has_pos ? (long)M_FINE * 3 : 0);
        const int has_batch = (rem >= (long)M_FINE) ? 1 : 0;
        const int nmax = has_pos ? M_FINE * 3 : M_FINE;
        tail_kernel<<<(nmax + 255) / 256, 256>>>(pos_skip, out, has_pos, has_batch);
    }
}

// round 5
// speedup vs baseline: 3.0658x; 1.5068x over previous
#include <cuda_runtime.h>
#include <cuda_fp16.h>
#include <cstdint>

// Problem constants
#define BB      16
#define NC      1024
#define NF      4096
#define M_FINE  (BB * NF)       // 65536
#define CIN     256
#define CSKIP   128
#define C0      384
#define HID     512

// ---------------------------------------------------------------------------
// Device scratch (no cudaMalloc allowed)
// ---------------------------------------------------------------------------
__device__ __half g_xi[(size_t)M_FINE * C0];     // fp16 activations (layer-1 input)
__device__ __half g_h1[(size_t)M_FINE * HID];    // fp16 hidden (layer-2 input)
__device__ __half g_wt1_h[HID * C0];             // [n][k] = w1[k][n] hi
__device__ __half g_wt1_l[HID * C0];             // residual lo
__device__ __half g_wt2_h[HID * HID];
__device__ __half g_wt2_l[HID * HID];
__device__ int   g_knn_idx[M_FINE * 3];
__device__ float g_knn_w[M_FINE * 3];

// ---------------------------------------------------------------------------
// Baseline-ISA tensor-core helpers (valid in compute_103 PTX)
// ---------------------------------------------------------------------------
__device__ __forceinline__ uint32_t smem_to_u32(const void* p) {
    uint32_t a;
    asm("{ .reg .u64 t; cvta.to.shared.u64 t, %1; cvt.u32.u64 %0, t; }" : "=r"(a) : "l"(p));
    return a;
}
__device__ __forceinline__ void cp_async16(uint32_t saddr, const void* gaddr) {
    asm volatile("cp.async.cg.shared.global [%0], [%1], 16;" :: "r"(saddr), "l"(gaddr));
}
#define CP_COMMIT() asm volatile("cp.async.commit_group;" ::: "memory")
#define CP_WAIT(N)  asm volatile("cp.async.wait_group %0;" :: "n"(N) : "memory")

__device__ __forceinline__ void ldsm_x4(uint32_t* r, uint32_t addr) {
    asm volatile("ldmatrix.sync.aligned.m8n8.x4.shared.b16 {%0,%1,%2,%3}, [%4];"
                 : "=r"(r[0]), "=r"(r[1]), "=r"(r[2]), "=r"(r[3]) : "r"(addr));
}
__device__ __forceinline__ void ldsm_x2(uint32_t* r, uint32_t addr) {
    asm volatile("ldmatrix.sync.aligned.m8n8.x2.shared.b16 {%0,%1}, [%2];"
                 : "=r"(r[0]), "=r"(r[1]) : "r"(addr));
}
__device__ __forceinline__ void mma_fp16(float* c, const uint32_t* a, const uint32_t* b) {
    asm volatile("mma.sync.aligned.m16n8k16.row.col.f32.f16.f16.f32 "
                 "{%0,%1,%2,%3}, {%4,%5,%6,%7}, {%8,%9}, {%0,%1,%2,%3};"
                 : "+f"(c[0]), "+f"(c[1]), "+f"(c[2]), "+f"(c[3])
                 : "r"(a[0]), "r"(a[1]), "r"(a[2]), "r"(a[3]), "r"(b[0]), "r"(b[1]));
}

// ---------------------------------------------------------------------------
// Weight prep (both layers in one launch): transpose + fp16 hi/lo split.
// wt[n][k] = w[k][n].  Coalesced reads (n fastest).
// ---------------------------------------------------------------------------
#define W1_ELEMS (C0 * HID)
#define W2_ELEMS (HID * HID)
__global__ void wprep_kernel(const float* __restrict__ w1, const float* __restrict__ w2) {
    const int i = blockIdx.x * blockDim.x + threadIdx.x;
    if (i < W1_ELEMS) {
        const int k = i / HID, n = i % HID;            // coalesced read of w1[k][n]
        const float v = w1[i];
        const __half h = __float2half(v);
        const __half l = __float2half(v - __half2float(h));
        g_wt1_h[(size_t)n * C0 + k] = h;
        g_wt1_l[(size_t)n * C0 + k] = l;
    } else if (i < W1_ELEMS + W2_ELEMS) {
        const int j = i - W1_ELEMS;
        const int k = j / HID, n = j % HID;
        const float v = w2[j];
        const __half h = __float2half(v);
        const __half l = __float2half(v - __half2float(h));
        g_wt2_h[(size_t)n * HID + k] = h;
        g_wt2_l[(size_t)n * HID + k] = l;
    }
}

// ---------------------------------------------------------------------------
// Kernel 1: brute-force kNN (K=3)
// ---------------------------------------------------------------------------
__global__ void knn_kernel(const float* __restrict__ pos,
                           const float* __restrict__ pos_skip) {
    __shared__ float sp[NC * 3];
    const int b = blockIdx.x;
    const float* pbase = pos + (size_t)b * NC * 3;
    for (int i = threadIdx.x; i < NC * 3; i += blockDim.x) sp[i] = pbase[i];
    __syncthreads();

    const int p = b * NF + blockIdx.y * blockDim.x + threadIdx.x;
    const float qx = pos_skip[(size_t)p * 3 + 0];
    const float qy = pos_skip[(size_t)p * 3 + 1];
    const float qz = pos_skip[(size_t)p * 3 + 2];

    float d0 = 1e30f, d1 = 1e30f, d2 = 1e30f;
    int   i0 = 0,     i1 = 0,     i2 = 0;
#pragma unroll 4
    for (int j = 0; j < NC; j++) {
        const float dx = qx - sp[j * 3 + 0];
        const float dy = qy - sp[j * 3 + 1];
        const float dz = qz - sp[j * 3 + 2];
        const float d  = dx * dx + dy * dy + dz * dz;
        if (d < d2) {
            if (d < d1) {
                d2 = d1; i2 = i1;
                if (d < d0) { d1 = d0; i1 = i0; d0 = d; i0 = j; }
                else        { d1 = d;  i1 = j; }
            } else { d2 = d; i2 = j; }
        }
    }
    const float w0 = 1.0f / fmaxf(d0, 1e-16f);
    const float w1 = 1.0f / fmaxf(d1, 1e-16f);
    const float w2 = 1.0f / fmaxf(d2, 1e-16f);
    const float inv = 1.0f / (w0 + w1 + w2);
    g_knn_idx[p * 3 + 0] = b * NC + i0;
    g_knn_idx[p * 3 + 1] = b * NC + i1;
    g_knn_idx[p * 3 + 2] = b * NC + i2;
    g_knn_w  [p * 3 + 0] = w0 * inv;
    g_knn_w  [p * 3 + 1] = w1 * inv;
    g_knn_w  [p * 3 + 2] = w2 * inv;
}

// ---------------------------------------------------------------------------
// Kernel 2: gather + interpolate + concat -> fp16 [M, 384]
// ---------------------------------------------------------------------------
__global__ void gather_kernel(const float* __restrict__ x,
                              const float* __restrict__ x_skip) {
    const int p = blockIdx.x;
    const int t = threadIdx.x;       // 128 threads
    const int   i0 = g_knn_idx[p * 3 + 0];
    const int   i1 = g_knn_idx[p * 3 + 1];
    const int   i2 = g_knn_idx[p * 3 + 2];
    const float w0 = g_knn_w[p * 3 + 0];
    const float w1 = g_knn_w[p * 3 + 1];
    const float w2 = g_knn_w[p * 3 + 2];

    const float2* r0 = (const float2*)(x + (size_t)i0 * CIN);
    const float2* r1 = (const float2*)(x + (size_t)i1 * CIN);
    const float2* r2 = (const float2*)(x + (size_t)i2 * CIN);
    __half* out = g_xi + (size_t)p * C0;
    // CIN = 256 -> 128 float2 pairs, one per thread
    {
        const float2 a = r0[t], b = r1[t], c = r2[t];
        const float v0 = w0 * a.x + w1 * b.x + w2 * c.x;
        const float v1 = w0 * a.y + w1 * b.y + w2 * c.y;
        *(__half2*)(out + 2 * t) = __floats2half2_rn(v0, v1);
    }
    // skip channels: 128 values, one per thread
    out[CIN + t] = __float2half(x_skip[(size_t)p * CSKIP + t]);
}

// ---------------------------------------------------------------------------
// Kernel 3: fp16 HMMA GEMM, 2-term weight hi/lo split.
// CTA tile 128x128, 8 warps (2m x 4n), warp 64x32, K-step 64.
// cp.async double-buffered, 144B-padded rows (conflict-free ldmatrix).
// Fused bias + ReLU + BN. OUT_HALF: emit fp16 for next layer.
// ---------------------------------------------------------------------------
#define RSTRIDE   144                         // 64 halves + 8 pad
#define TILE_B    (128 * RSTRIDE)             // 18432 B
#define STAGE_B   (3 * TILE_B)                // A | WH | WL = 55296 B
#define SMEM_GEMM (2 * STAGE_B)               // 110592 B -> 2 CTAs/SM

template <int KD, int OUT_HALF>
__global__ void __launch_bounds__(256, 2)
gemm_mma(const __half* __restrict__ A,
         const __half* __restrict__ Wh, const __half* __restrict__ Wl,
         const float* __restrict__ bias, const float* __restrict__ gam,
         const float* __restrict__ bet,  const float* __restrict__ mu,
         const float* __restrict__ var,
         float* __restrict__ Cf, __half* __restrict__ Ch) {
    extern __shared__ char smem[];
    const uint32_t sbase = smem_to_u32(smem);
    const int tid  = threadIdx.x;
    const int wid  = tid >> 5, lane = tid & 31;
    const int wm   = wid >> 2;          // 0..1
    const int wn   = wid & 3;           // 0..3
    const int bm0  = blockIdx.y * 128;
    const int bn0  = blockIdx.x * 128;

    const int crow  = tid >> 1;                // 0..127
    const int cseg0 = (tid & 1) * 4;           // 0 or 4

    auto load_stage = [&](int kt, int buf) {
        const int k0 = kt * 64;
        const uint32_t stg = sbase + buf * STAGE_B;
        const size_t ga = (size_t)(bm0 + crow) * KD + k0 + cseg0 * 8;
        const size_t gb = (size_t)(bn0 + crow) * KD + k0 + cseg0 * 8;
        const uint32_t so = crow * RSTRIDE + cseg0 * 16;
#pragma unroll
        for (int s = 0; s < 4; s++) {
            cp_async16(stg + 0 * TILE_B + so + s * 16, A  + ga + s * 8);
            cp_async16(stg + 1 * TILE_B + so + s * 16, Wh + gb + s * 8);
            cp_async16(stg + 2 * TILE_B + so + s * 16, Wl + gb + s * 8);
        }
    };

    float acc[4][4][4] = {};   // [mi][ni][frag]

    const uint32_t a_row  = wm * 64 + (lane & 15);
    const uint32_t a_colb = (lane >> 4) * 16;
    const uint32_t b_row  = wn * 32 + (lane & 7);
    const uint32_t b_colb = ((lane >> 3) & 1) * 16;

    load_stage(0, 0);
    CP_COMMIT();

    constexpr int NT = KD / 64;
#pragma unroll 1
    for (int t = 0; t < NT; t++) {
        if (t + 1 < NT) { load_stage(t + 1, (t + 1) & 1); CP_COMMIT(); CP_WAIT(1); }
        else            { CP_WAIT(0); }
        __syncthreads();

        const uint32_t stg = sbase + (t & 1) * STAGE_B;
        const uint32_t a_base  = stg + 0 * TILE_B;
        const uint32_t wh_base = stg + 1 * TILE_B;
        const uint32_t wl_base = stg + 2 * TILE_B;

#pragma unroll
        for (int kf = 0; kf < 4; kf++) {
            uint32_t af[4][4], bh[4][2], bl[4][2];
#pragma unroll
            for (int mi = 0; mi < 4; mi++) {
                const uint32_t ao = (a_row + mi * 16) * RSTRIDE + kf * 32 + a_colb;
                ldsm_x4(af[mi], a_base + ao);
            }
#pragma unroll
            for (int ni = 0; ni < 4; ni++) {
                const uint32_t bo = (b_row + ni * 8) * RSTRIDE + kf * 32 + b_colb;
                ldsm_x2(bh[ni], wh_base + bo);
                ldsm_x2(bl[ni], wl_base + bo);
            }
#pragma unroll
            for (int mi = 0; mi < 4; mi++)
#pragma unroll
                for (int ni = 0; ni < 4; ni++) {
                    mma_fp16(acc[mi][ni], af[mi], bh[ni]);
                    mma_fp16(acc[mi][ni], af[mi], bl[ni]);
                }
        }
        __syncthreads();
    }

    // ----- fused epilogue: bias -> ReLU -> BN -----
#pragma unroll
    for (int ni = 0; ni < 4; ni++) {
        const int c0 = bn0 + wn * 32 + ni * 8 + (lane & 3) * 2;
        const float sa = gam[c0]     * rsqrtf(var[c0]     + 1e-5f);
        const float sb = gam[c0 + 1] * rsqrtf(var[c0 + 1] + 1e-5f);
        const float sh0 = bet[c0]     - mu[c0]     * sa;
        const float sh1 = bet[c0 + 1] - mu[c0 + 1] * sb;
        const float bb0 = bias[c0], bb1 = bias[c0 + 1];
#pragma unroll
        for (int mi = 0; mi < 4; mi++) {
#pragma unroll
            for (int half = 0; half < 2; half++) {
                const int row = bm0 + wm * 64 + mi * 16 + (lane >> 2) + half * 8;
                const float v0 = fmaf(fmaxf(acc[mi][ni][half * 2 + 0] + bb0, 0.0f), sa, sh0);
                const float v1 = fmaf(fmaxf(acc[mi][ni][half * 2 + 1] + bb1, 0.0f), sb, sh1);
                if (OUT_HALF) {
                    *(__half2*)(Ch + (size_t)row * HID + c0) = __floats2half2_rn(v0, v1);
                } else {
                    float2 o; o.x = v0; o.y = v1;
                    *(float2*)(Cf + (size_t)row * HID + c0) = o;
                }
            }
        }
    }
}

// ---------------------------------------------------------------------------
// Optional tail (pos_skip / batch_skip passthrough)
// ---------------------------------------------------------------------------
__global__ void tail_kernel(const float* __restrict__ pos_skip, float* __restrict__ out,
                            int has_pos, int has_batch) {
    const int i = blockIdx.x * blockDim.x + threadIdx.x;
    size_t off = (size_t)M_FINE * HID;
    if (has_pos) {
        if (i < M_FINE * 3) out[off + i] = pos_skip[i];
        off += (size_t)M_FINE * 3;
    }
    if (has_batch) {
        if (i < M_FINE) out[off + i] = (float)(i / NF);
    }
}

// ---------------------------------------------------------------------------
extern "C" void kernel_launch(void* const* d_in, const int* in_sizes, int n_in,
                              void* d_out, int out_size) {
    const float* x        = (const float*)d_in[0];
    const float* pos      = (const float*)d_in[1];
    const float* x_skip   = (const float*)d_in[3];
    const float* pos_skip = (const float*)d_in[4];
    const float* w1  = (const float*)d_in[6];
    const float* b1  = (const float*)d_in[7];
    const float* g1  = (const float*)d_in[8];
    const float* be1 = (const float*)d_in[9];
    const float* m1  = (const float*)d_in[10];
    const float* v1  = (const float*)d_in[11];
    const float* w2  = (const float*)d_in[12];
    const float* b2  = (const float*)d_in[13];
    const float* g2  = (const float*)d_in[14];
    const float* be2 = (const float*)d_in[15];
    const float* m2  = (const float*)d_in[16];
    const float* v2  = (const float*)d_in[17];
    float* out = (float*)d_out;

    static __half *xi = nullptr, *h1, *wt1_h, *wt1_l, *wt2_h, *wt2_l;
    if (!xi) {
        cudaGetSymbolAddress((void**)&xi, g_xi);
        cudaGetSymbolAddress((void**)&h1, g_h1);
        cudaGetSymbolAddress((void**)&wt1_h, g_wt1_h);
        cudaGetSymbolAddress((void**)&wt1_l, g_wt1_l);
        cudaGetSymbolAddress((void**)&wt2_h, g_wt2_h);
        cudaGetSymbolAddress((void**)&wt2_l, g_wt2_l);
        cudaFuncSetAttribute(gemm_mma<C0, 1>,  cudaFuncAttributeMaxDynamicSharedMemorySize, SMEM_GEMM);
        cudaFuncSetAttribute(gemm_mma<HID, 0>, cudaFuncAttributeMaxDynamicSharedMemorySize, SMEM_GEMM);
    }

    // 0) weight prep (transpose + fp16 hi/lo split), one launch
    wprep_kernel<<<(W1_ELEMS + W2_ELEMS + 255) / 256, 256>>>(w1, w2);
    // 1) kNN
    knn_kernel<<<dim3(BB, NF / 256), 256>>>(pos, pos_skip);
    // 2) interpolate + concat (fp16)
    gather_kernel<<<M_FINE, 128>>>(x, x_skip);
    // 3) MLP block 1: [M,384] @ [384,512] -> h1 (fp16)
    gemm_mma<C0, 1><<<dim3(HID / 128, M_FINE / 128), 256, SMEM_GEMM>>>(
        xi, wt1_h, wt1_l, b1, g1, be1, m1, v1, nullptr, h1);
    // 4) MLP block 2: [M,512] @ [512,512] -> d_out (fp32)
    gemm_mma<HID, 0><<<dim3(HID / 128, M_FINE / 128), 256, SMEM_GEMM>>>(
        h1, wt2_h, wt2_l, b2, g2, be2, m2, v2, out, nullptr);

    // 5) optional passthrough outputs
    const long extra = (long)out_size - (long)M_FINE * HID;
    if (extra > 0) {
        const int has_pos   = (extra >= (long)M_FINE * 3) ? 1 : 0;
        const long rem      = extra - (has_pos ? (long)M_FINE * 3 : 0);
        const int has_batch = (rem >= (long)M_FINE) ? 1 : 0;
        const int nmax = has_pos ? M_FINE * 3 : M_FINE;
        tail_kernel<<<(nmax + 255) / 256, 256>>>(pos_skip, out, has_pos, has_batch);
    }
}